// round 15
// baseline (speedup 1.0000x reference)
#include <cuda_runtime.h>
#include <cuda_bf16.h>
#include <cuda_fp16.h>
#include <stdint.h>
#include <math.h>

#define BN 8
#define TT 1024
#define CCH 768
#define HH 12
#define HSZ 64
#define EE 8
#define FF 3072
#define NT (BN*TT)
#define BH (BN*HH)
typedef __nv_bfloat16 bf16;
typedef __half f16;

// ---- static scratch ----
__device__ bf16  g_qh[BH*TT*HSZ], g_ql[BH*TT*HSZ];
__device__ bf16  g_kh[BH*TT*HSZ], g_kl[BH*TT*HSZ];
__device__ bf16  g_vh[BH*TT*HSZ], g_vl[BH*TT*HSZ];
__device__ bf16  g_h1h[NT*CCH], g_h1l[NT*CCH];
__device__ bf16  g_aoh[NT*CCH], g_aol[NT*CCH];
__device__ float g_x2[NT*CCH];
__device__ float g_h2[NT*CCH];
__device__ f16   g_h2f[NT*CCH];
__device__ float g_gw[NT*2];
__device__ int   g_pos[NT*2];
__device__ int   g_tok[EE*NT];
__device__ int   g_cnt[EE];
__device__ f16   g_t1f[(size_t)EE*NT*FF];
__device__ f16   g_t2f[(size_t)2*NT*FF];
__device__ float g_t3[(size_t)EE*NT*CCH];
__device__ bf16  g_Bqh[3*CCH*CCH], g_Bql[3*CCH*CCH];
__device__ bf16  g_Bph[CCH*CCH],  g_Bpl[CCH*CCH];
__device__ f16   g_Bd1[2*CCH*FF];
__device__ f16   g_Bd2[(size_t)2*FF*FF];
__device__ f16   g_Bd3[2*CCH*FF];
__device__ f16   g_Bs1[(size_t)6*CCH*FF];
__device__ f16   g_Bs2[(size_t)6*CCH*FF];

__device__ __forceinline__ float geluf(float v){
    return 0.5f*v*(1.f + erff(v*0.70710678118654752440f));
}
__device__ __forceinline__ uint32_t smem_u32(const void* p){
    uint32_t a;
    asm("{ .reg .u64 t; cvta.to.shared.u64 t, %1; cvt.u32.u64 %0, t; }" : "=r"(a) : "l"(p));
    return a;
}
__device__ __forceinline__ void cp16(uint32_t d, const void* s){
    asm volatile("cp.async.cg.shared.global [%0], [%1], 16;" :: "r"(d), "l"(s));
}
__device__ __forceinline__ void ldsm4(uint32_t a, uint32_t* r){
    asm volatile("ldmatrix.sync.aligned.m8n8.x4.shared.b16 {%0,%1,%2,%3}, [%4];"
        : "=r"(r[0]),"=r"(r[1]),"=r"(r[2]),"=r"(r[3]) : "r"(a));
}
__device__ __forceinline__ void ldsm4t(uint32_t a, uint32_t* r){
    asm volatile("ldmatrix.sync.aligned.m8n8.x4.trans.shared.b16 {%0,%1,%2,%3}, [%4];"
        : "=r"(r[0]),"=r"(r[1]),"=r"(r[2]),"=r"(r[3]) : "r"(a));
}
__device__ __forceinline__ void mma16816(float* c, const uint32_t* a, const uint32_t* b){
    asm volatile("mma.sync.aligned.m16n8k16.row.col.f32.bf16.bf16.f32 "
        "{%0,%1,%2,%3},{%4,%5,%6,%7},{%8,%9},{%0,%1,%2,%3};"
        : "+f"(c[0]),"+f"(c[1]),"+f"(c[2]),"+f"(c[3])
        : "r"(a[0]),"r"(a[1]),"r"(a[2]),"r"(a[3]), "r"(b[0]),"r"(b[1]));
}
__device__ __forceinline__ void mmah16816(float* c, const uint32_t* a, const uint32_t* b){
    asm volatile("mma.sync.aligned.m16n8k16.row.col.f32.f16.f16.f32 "
        "{%0,%1,%2,%3},{%4,%5,%6,%7},{%8,%9},{%0,%1,%2,%3};"
        : "+f"(c[0]),"+f"(c[1]),"+f"(c[2]),"+f"(c[3])
        : "r"(a[0]),"r"(a[1]),"r"(a[2]),"r"(a[3]), "r"(b[0]),"r"(b[1]));
}
__device__ __forceinline__ uint32_t packbf(float a, float b){
    __nv_bfloat162 p; p.x=__float2bfloat16(a); p.y=__float2bfloat16(b);
    return *reinterpret_cast<uint32_t*>(&p);
}

__global__ void k_reset(){ if(threadIdx.x < EE) g_cnt[threadIdx.x] = 0; }

// W[K][N] -> out[N][K] hi/lo bf16 (attention weights)
__global__ void k_wsplit2(const float* __restrict__ W, bf16* __restrict__ oh,
                          bf16* __restrict__ ol, int K, int N){
    int e = blockIdx.z;
    W += (size_t)e*K*N; oh += (size_t)e*K*N; ol += (size_t)e*K*N;
    __shared__ float s[64][33];
    int n0 = blockIdx.x*32, k0 = blockIdx.y*64;
    int tx = threadIdx.x, ty = threadIdx.y;
#pragma unroll
    for(int r=0;r<8;r++){ int kk=ty+r*8; s[kk][tx] = W[(size_t)(k0+kk)*N + n0+tx]; }
    __syncthreads();
#pragma unroll
    for(int r=0;r<4;r++){
        int n = ty + r*8;
        float v0 = s[2*tx][n], v1 = s[2*tx+1][n];
        bf16 h0 = __float2bfloat16(v0), h1 = __float2bfloat16(v1);
        bf16 hh[2] = {h0, h1};
        bf16 ll[2] = {__float2bfloat16(v0-__bfloat162float(h0)),
                      __float2bfloat16(v1-__bfloat162float(h1))};
        size_t o = (size_t)(n0+n)*K + k0 + 2*tx;
        *reinterpret_cast<uint32_t*>(&oh[o]) = *reinterpret_cast<uint32_t*>(hh);
        *reinterpret_cast<uint32_t*>(&ol[o]) = *reinterpret_cast<uint32_t*>(ll);
    }
}

// W[K][N] -> out[N][K] single fp16 (expert weights)
__global__ void k_wcvt(const float* __restrict__ W, f16* __restrict__ oh, int K, int N){
    int e = blockIdx.z;
    W += (size_t)e*K*N; oh += (size_t)e*K*N;
    __shared__ float s[64][33];
    int n0 = blockIdx.x*32, k0 = blockIdx.y*64;
    int tx = threadIdx.x, ty = threadIdx.y;
#pragma unroll
    for(int r=0;r<8;r++){ int kk=ty+r*8; s[kk][tx] = W[(size_t)(k0+kk)*N + n0+tx]; }
    __syncthreads();
#pragma unroll
    for(int r=0;r<4;r++){
        int n = ty + r*8;
        __half2 hp; hp.x=__float2half(s[2*tx][n]); hp.y=__float2half(s[2*tx+1][n]);
        size_t o = (size_t)(n0+n)*K + k0 + 2*tx;
        *reinterpret_cast<__half2*>(&oh[o]) = hp;
    }
}

__global__ void k_ln(const float* __restrict__ in, const float* __restrict__ gam,
                     const float* __restrict__ bet, float* __restrict__ out,
                     bf16* __restrict__ oh, bf16* __restrict__ ol, f16* __restrict__ of){
    int n = blockIdx.x, t = threadIdx.x;
    const float* row = in + (size_t)n*CCH;
    float v[3], s=0.f, s2=0.f;
#pragma unroll
    for(int i=0;i<3;i++){ v[i]=row[t+256*i]; s+=v[i]; s2+=v[i]*v[i]; }
    __shared__ float shs[8], shq[8];
#pragma unroll
    for(int o=16;o;o>>=1){ s+=__shfl_xor_sync(~0u,s,o); s2+=__shfl_xor_sync(~0u,s2,o); }
    if((t&31)==0){ shs[t>>5]=s; shq[t>>5]=s2; }
    __syncthreads();
    s=0.f; s2=0.f;
#pragma unroll
    for(int i=0;i<8;i++){ s+=shs[i]; s2+=shq[i]; }
    float mean=s*(1.f/768.f), var=s2*(1.f/768.f)-mean*mean, r=rsqrtf(var+1e-5f);
#pragma unroll
    for(int i=0;i<3;i++){
        int c=t+256*i;
        float o=(v[i]-mean)*r*gam[c]+bet[c];
        if(out) out[(size_t)n*CCH+c]=o;
        if(oh){
            bf16 hi=__float2bfloat16(o);
            oh[(size_t)n*CCH+c]=hi;
            ol[(size_t)n*CCH+c]=__float2bfloat16(o-__bfloat162float(hi));
        }
        if(of) of[(size_t)n*CCH+c]=__float2half(o);
    }
}

// fused LN2 + noisy top-2 router (block per token)
__global__ void k_lnrouter(const float* __restrict__ in, const float* __restrict__ gam,
                           const float* __restrict__ bet,
                           const float* __restrict__ wr, const float* __restrict__ br,
                           const float* __restrict__ wn, const float* __restrict__ bnn,
                           const float* __restrict__ temp, const float* __restrict__ noise){
    int n = blockIdx.x, t = threadIdx.x, lane = t&31, warp = t>>5;
    const float* row = g_x2 + (size_t)n*CCH;
    float v[3], s=0.f, s2=0.f;
    (void)in;
#pragma unroll
    for(int i=0;i<3;i++){ v[i]=row[t+256*i]; s+=v[i]; s2+=v[i]*v[i]; }
    __shared__ float shs[8], shq[8];
#pragma unroll
    for(int o=16;o;o>>=1){ s+=__shfl_xor_sync(~0u,s,o); s2+=__shfl_xor_sync(~0u,s2,o); }
    if(lane==0){ shs[warp]=s; shq[warp]=s2; }
    __syncthreads();
    s=0.f; s2=0.f;
#pragma unroll
    for(int i=0;i<8;i++){ s+=shs[i]; s2+=shq[i]; }
    float mean=s*(1.f/768.f), var=s2*(1.f/768.f)-mean*mean, r=rsqrtf(var+1e-5f);
    float acc[16];
#pragma unroll
    for(int j=0;j<16;j++) acc[j]=0.f;
#pragma unroll
    for(int i=0;i<3;i++){
        int c=t+256*i;
        float o=(v[i]-mean)*r*gam[c]+bet[c];
        g_h2[(size_t)n*CCH+c]=o;
        g_h2f[(size_t)n*CCH+c]=__float2half(o);
        const float* wrp=wr+c*EE; const float* wnp=wn+c*EE;
#pragma unroll
        for(int e=0;e<8;e++){ acc[e]+=o*wrp[e]; acc[8+e]+=o*wnp[e]; }
    }
#pragma unroll
    for(int o=16;o;o>>=1)
#pragma unroll
        for(int j=0;j<16;j++) acc[j]+=__shfl_xor_sync(~0u,acc[j],o);
    __shared__ float sh2[8][16];
    if(lane==0)
#pragma unroll
        for(int j=0;j<16;j++) sh2[warp][j]=acc[j];
    __syncthreads();
    if(t==0){
        float ny[8];
#pragma unroll
        for(int e=0;e<8;e++){
            float rr=0.f, qq=0.f;
#pragma unroll
            for(int w2=0;w2<8;w2++){ rr+=sh2[w2][e]; qq+=sh2[w2][8+e]; }
            float tc=fminf(fmaxf(temp[0],0.5f),2.0f);
            float z=qq+bnn[e];
            float sp=(z>20.f)? z : log1pf(expf(z));
            ny[e]=rr+br[e] + tc*noise[(size_t)n*EE+e]*sp;
        }
        int i1=0;
#pragma unroll
        for(int e=1;e<8;e++) if(ny[e]>ny[i1]) i1=e;
        int i2=-1;
#pragma unroll
        for(int e=0;e<8;e++){ if(e==i1) continue; if(i2<0||ny[e]>ny[i2]) i2=e; }
        float e2=expf(ny[i2]-ny[i1]);
        float gv[2]={1.f/(1.f+e2), e2/(1.f+e2)};
        int id[2]={i1,i2};
#pragma unroll
        for(int k2=0;k2<2;k2++){
            int e=id[k2];
            int rw=atomicAdd(&g_cnt[e],1);
            g_tok[e*NT+rw]=n;
            g_pos[n*2+k2]=e*NT+rw;
            g_gw[n*2+k2]=gv[k2];
        }
    }
}

// ---- bf16 3-product GEMM (QKV + proj), 2-stage, 2 CTAs/SM ----
#define PITCH 80
#define TILEB 10240
#define STAGEB 40960
#define SMEMSZ (2*STAGEB)
template<int EPI>
__global__ void __launch_bounds__(256,2)
k_mma(const bf16* __restrict__ Ah, const bf16* __restrict__ Al,
      const bf16* __restrict__ Bh, const bf16* __restrict__ Bl,
      const float* __restrict__ bias, const float* __restrict__ resid,
      float* __restrict__ out32, int M, int Nn, int K){
    int by = blockIdx.y, bx = blockIdx.x;
    extern __shared__ char smem[];
    uint32_t su = smem_u32(smem);
    int tid=threadIdx.x, lane=tid&31, wid=tid>>5;
    int wm=wid&3, wn=wid>>2;
    const int KT = K/32;
    float acc[2][8][4];
#pragma unroll
    for(int a=0;a<2;a++)
#pragma unroll
        for(int b=0;b<8;b++)
#pragma unroll
            for(int c=0;c<4;c++) acc[a][b][c]=0.f;
    auto load_stage = [&](int kt){
        uint32_t sb = su + (kt&1)*STAGEB;
#pragma unroll
        for(int i=0;i<8;i++){
            int c = tid + i*256;
            int tile=c>>9, w=c&511, row=w>>2, q=w&3;
            uint32_t d = sb + tile*TILEB + row*PITCH + q*16;
            const bf16* src;
            if(tile<2) src = (tile==0?Ah:Al) + (size_t)(by*128+row)*K + kt*32 + q*8;
            else       src = (tile==2?Bh:Bl) + (size_t)(bx*128+row)*K + kt*32 + q*8;
            cp16(d, src);
        }
        asm volatile("cp.async.commit_group;" ::: "memory");
    };
    load_stage(0);
    for(int kt=0; kt<KT; kt++){
        if(kt+1<KT){
            load_stage(kt+1);
            asm volatile("cp.async.wait_group 1;" ::: "memory");
        } else {
            asm volatile("cp.async.wait_group 0;" ::: "memory");
        }
        __syncthreads();
        uint32_t sb = su + (kt&1)*STAGEB;
#pragma unroll
        for(int kh=0; kh<2; kh++){
            uint32_t aH[2][4], aL[2][4];
            int arow = wm*32 + (lane&15);
            uint32_t ako = kh*32 + (lane>>4)*16;
#pragma unroll
            for(int mt=0;mt<2;mt++){
                uint32_t ad = sb + (arow+mt*16)*PITCH + ako;
                ldsm4(ad, aH[mt]); ldsm4(ad + TILEB, aL[mt]);
            }
            uint32_t bHf[4][4], bLf[4][4];
            int brow = wn*64 + ((lane&7) | ((lane&16)>>1));
            uint32_t bko = kh*32 + ((lane>>3)&1)*16;
#pragma unroll
            for(int nt=0;nt<4;nt++){
                uint32_t bd = sb + 2*TILEB + (brow+nt*16)*PITCH + bko;
                ldsm4(bd, bHf[nt]); ldsm4(bd + TILEB, bLf[nt]);
            }
#pragma unroll
            for(int mt=0;mt<2;mt++)
#pragma unroll
            for(int n8=0;n8<8;n8++){
                uint32_t* bh = &bHf[n8>>1][(n8&1)*2];
                uint32_t* bl = &bLf[n8>>1][(n8&1)*2];
                mma16816(acc[mt][n8], aH[mt], bh);
                mma16816(acc[mt][n8], aH[mt], bl);
                mma16816(acc[mt][n8], aL[mt], bh);
            }
        }
        __syncthreads();
    }
    int g = lane>>2, t4 = lane&3;
#pragma unroll
    for(int mt=0;mt<2;mt++)
#pragma unroll
    for(int n8=0;n8<8;n8++){
        int col = bx*128 + wn*64 + n8*8 + t4*2;
#pragma unroll
        for(int hf=0; hf<2; hf++){
            int row = by*128 + wm*32 + mt*16 + g + hf*8;
            float v0 = acc[mt][n8][hf*2+0];
            float v1 = acc[mt][n8][hf*2+1];
            if(EPI==0){
                int which = col/CCH, rem = col - which*CCH;
                int h = rem>>6, d0 = rem&63;
                int b = row>>10, t = row&1023;
                size_t o = ((size_t)(b*HH+h)*TT + t)*HSZ + d0;
                bf16* dh = which==0? g_qh : which==1? g_kh : g_vh;
                bf16* dl = which==0? g_ql : which==1? g_kl : g_vl;
                bf16 h0=__float2bfloat16(v0), h1=__float2bfloat16(v1);
                __nv_bfloat162 hp; hp.x=h0; hp.y=h1;
                __nv_bfloat162 lp;
                lp.x=__float2bfloat16(v0-__bfloat162float(h0));
                lp.y=__float2bfloat16(v1-__bfloat162float(h1));
                *reinterpret_cast<__nv_bfloat162*>(&dh[o]) = hp;
                *reinterpret_cast<__nv_bfloat162*>(&dl[o]) = lp;
            } else {
                size_t o=(size_t)row*Nn+col;
                out32[o]   = v0 + bias[col]   + resid[o];
                out32[o+1] = v1 + bias[col+1] + resid[o+1];
            }
        }
    }
}

// ---- fp16 single-product GEMM (experts), 3-stage, 2 CTAs/SM, z-batched ----
#define HSTG (2*TILEB)
#define HSMEM (3*HSTG)
template<int EPI>
__global__ void __launch_bounds__(256,2)
k_mmah(const f16* __restrict__ A1, size_t zsA, const f16* __restrict__ A2, size_t zsA2,
       int zSplitA, int zOff,
       const f16* __restrict__ B1, const f16* __restrict__ B2, size_t zsB, int zSplit,
       const float* __restrict__ b1, const float* __restrict__ b2,
       float* __restrict__ out32, f16* __restrict__ outH, size_t zsOut,
       int M, int Nn, int K,
       const int* __restrict__ tok, const int* __restrict__ cnt){
    int z = blockIdx.z + zOff;
    if(cnt) M = cnt[z];
    int by = blockIdx.y, bx = blockIdx.x;
    if(by*128 >= M) return;
    const f16* A = (z < zSplitA) ? A1 + (size_t)z*zsA : A2 + (size_t)z*zsA2;
    const f16* Bp; const float* bias;
    if(z < zSplit){ Bp=B1+(size_t)z*zsB; bias=b1+(size_t)z*Nn; }
    else { Bp=B2+(size_t)(z-zSplit)*zsB; bias=b2+(size_t)(z-zSplit)*Nn; }
    if(out32) out32 += (size_t)z*zsOut;
    if(outH)  outH  += (size_t)z*zsOut;
    if(tok) tok += (size_t)z*NT;
    extern __shared__ char smem[];
    uint32_t su = smem_u32(smem);
    int tid=threadIdx.x, lane=tid&31, wid=tid>>5;
    int wm=wid&3, wn=wid>>2;
    const int KT = K/32;
    float acc[2][8][4];
#pragma unroll
    for(int a=0;a<2;a++)
#pragma unroll
        for(int b=0;b<8;b++)
#pragma unroll
            for(int c=0;c<4;c++) acc[a][b][c]=0.f;
    auto load_stage = [&](int kt){
        uint32_t sb = su + (kt%3)*HSTG;
#pragma unroll
        for(int i=0;i<4;i++){
            int c = tid + i*256;
            int tile=c>>9, w=c&511, row=w>>2, q=w&3;
            uint32_t d = sb + tile*TILEB + row*PITCH + q*16;
            const f16* src;
            if(tile==0){
                int rg=by*128+row; if(rg>=M) rg=M-1;
                int asrc = tok ? tok[rg] : rg;
                src = A + (size_t)asrc*K + kt*32 + q*8;
            } else {
                src = Bp + (size_t)(bx*128+row)*K + kt*32 + q*8;
            }
            cp16(d, src);
        }
        asm volatile("cp.async.commit_group;" ::: "memory");
    };
    load_stage(0);
    if(KT>1) load_stage(1);
    for(int kt=0; kt<KT; kt++){
        if(kt+2<KT) load_stage(kt+2);
        if(kt+2<KT)      asm volatile("cp.async.wait_group 2;" ::: "memory");
        else if(kt+1<KT) asm volatile("cp.async.wait_group 1;" ::: "memory");
        else             asm volatile("cp.async.wait_group 0;" ::: "memory");
        __syncthreads();
        uint32_t sb = su + (kt%3)*HSTG;
#pragma unroll
        for(int kh=0; kh<2; kh++){
            uint32_t aF[2][4];
            int arow = wm*32 + (lane&15);
            uint32_t ako = kh*32 + (lane>>4)*16;
#pragma unroll
            for(int mt=0;mt<2;mt++)
                ldsm4(sb + (arow+mt*16)*PITCH + ako, aF[mt]);
            uint32_t bF[4][4];
            int brow = wn*64 + ((lane&7) | ((lane&16)>>1));
            uint32_t bko = kh*32 + ((lane>>3)&1)*16;
#pragma unroll
            for(int nt=0;nt<4;nt++)
                ldsm4(sb + TILEB + (brow+nt*16)*PITCH + bko, bF[nt]);
#pragma unroll
            for(int mt=0;mt<2;mt++)
#pragma unroll
            for(int n8=0;n8<8;n8++)
                mmah16816(acc[mt][n8], aF[mt], &bF[n8>>1][(n8&1)*2]);
        }
        __syncthreads();
    }
    int g = lane>>2, t4 = lane&3;
#pragma unroll
    for(int mt=0;mt<2;mt++)
#pragma unroll
    for(int n8=0;n8<8;n8++){
        int col = bx*128 + wn*64 + n8*8 + t4*2;
#pragma unroll
        for(int hf=0; hf<2; hf++){
            int row = by*128 + wm*32 + mt*16 + g + hf*8;
            if(row >= M) continue;
            float v0 = acc[mt][n8][hf*2+0];
            float v1 = acc[mt][n8][hf*2+1];
            size_t o=(size_t)row*Nn+col;
            if(EPI==2){
                __half2 hp;
                hp.x = __float2half(geluf(v0 + bias[col]));
                hp.y = __float2half(geluf(v1 + bias[col+1]));
                *reinterpret_cast<__half2*>(&outH[o]) = hp;
            } else {
                out32[o]   = v0 + bias[col];
                out32[o+1] = v1 + bias[col+1];
            }
        }
    }
}

// ---- flash attention v2 ----
#define FP2 144
#define QT (128*FP2)
#define KT2 (64*FP2)
#define STG2 (4*KT2)
#define FSM2 (2*QT + 2*STG2)
__global__ void __launch_bounds__(256,1) k_flash(){
    int tb = 7 - blockIdx.x, bh = blockIdx.y;
    extern __shared__ char fsm[];
    uint32_t su = smem_u32(fsm);
    uint32_t qb = su, kvb = su + 2*QT;
    int tid=threadIdx.x, lane=tid&31, w=tid>>5;
    const size_t hb = (size_t)bh*TT*HSZ;
#pragma unroll
    for(int i=0;i<8;i++){
        int c = tid + i*256;
        int half = c>>10, w2 = c&1023, row = w2>>3, q = w2&7;
        cp16(qb + half*QT + row*FP2 + q*16,
             (half? g_ql : g_qh) + hb + (size_t)(tb*128+row)*HSZ + q*8);
    }
    auto loadKV = [&](int sb){
        uint32_t base = kvb + (sb&1)*STG2;
#pragma unroll
        for(int i=0;i<8;i++){
            int c = tid + i*256;
            int arr = c>>9, w2 = c&511, row = w2>>3, q = w2&7;
            const bf16* src = (arr==0? g_kh : arr==1? g_kl : arr==2? g_vh : g_vl)
                            + hb + (size_t)(sb*64+row)*HSZ + q*8;
            cp16(base + arr*KT2 + row*FP2 + q*16, src);
        }
        asm volatile("cp.async.commit_group;" ::: "memory");
    };
    loadKV(0);
    float m0=-1e30f, m1=-1e30f, l0=0.f, l1=0.f;
    float O[8][4];
#pragma unroll
    for(int n8=0;n8<8;n8++)
#pragma unroll
        for(int c=0;c<4;c++) O[n8][c]=0.f;
    const float scale=0.036084391824351615f;
    int brow = (lane&7) | ((lane&16)>>1);
    int t4 = lane&3, g = lane>>2;
    int smax = 2*tb+1;
    for(int sb=0; sb<=smax; sb++){
        if(sb<smax) loadKV(sb+1);
        if(sb<smax) asm volatile("cp.async.wait_group 1;" ::: "memory");
        else        asm volatile("cp.async.wait_group 0;" ::: "memory");
        __syncthreads();
        uint32_t kb = kvb + (sb&1)*STG2;
        uint32_t vb = kb + 2*KT2;
        float S[8][4];
#pragma unroll
        for(int n8=0;n8<8;n8++)
#pragma unroll
            for(int c=0;c<4;c++) S[n8][c]=0.f;
#pragma unroll
        for(int kc=0;kc<4;kc++){
            uint32_t aH[4], aL[4];
            uint32_t ad = qb + (w*16+(lane&15))*FP2 + kc*32 + (lane>>4)*16;
            ldsm4(ad, aH); ldsm4(ad+QT, aL);
            uint32_t bHt[4][4], bLt[4][4];
#pragma unroll
            for(int nt=0;nt<4;nt++){
                uint32_t bd = kb + (nt*16+brow)*FP2 + kc*32 + ((lane>>3)&1)*16;
                ldsm4(bd, bHt[nt]); ldsm4(bd+KT2, bLt[nt]);
            }
#pragma unroll
            for(int n8=0;n8<8;n8++){
                uint32_t* bh2=&bHt[n8>>1][(n8&1)*2];
                uint32_t* bl2=&bLt[n8>>1][(n8&1)*2];
                mma16816(S[n8], aH, bh2);
                mma16816(S[n8], aH, bl2);
                mma16816(S[n8], aL, bh2);
            }
        }
        int rg0 = tb*128 + w*16 + g;
#pragma unroll
        for(int n8=0;n8<8;n8++)
#pragma unroll
            for(int c=0;c<4;c++){
                S[n8][c] *= scale;
                if(sb >= 2*tb){
                    int sg = sb*64 + n8*8 + t4*2 + (c&1);
                    int rg = rg0 + ((c>=2)?8:0);
                    if(sg > rg) S[n8][c] = -1e30f;
                }
            }
        float mx0=-1e30f, mx1=-1e30f;
#pragma unroll
        for(int n8=0;n8<8;n8++){
            mx0=fmaxf(mx0,fmaxf(S[n8][0],S[n8][1]));
            mx1=fmaxf(mx1,fmaxf(S[n8][2],S[n8][3]));
        }
        mx0=fmaxf(mx0,__shfl_xor_sync(~0u,mx0,1)); mx0=fmaxf(mx0,__shfl_xor_sync(~0u,mx0,2));
        mx1=fmaxf(mx1,__shfl_xor_sync(~0u,mx1,1)); mx1=fmaxf(mx1,__shfl_xor_sync(~0u,mx1,2));
        float mn0=fmaxf(m0,mx0), mn1=fmaxf(m1,mx1);
        float f0=expf(m0-mn0), f1=expf(m1-mn1);
        m0=mn0; m1=mn1;
        float rs0=0.f, rs1=0.f;
#pragma unroll
        for(int n8=0;n8<8;n8++){
            S[n8][0]=expf(S[n8][0]-mn0); S[n8][1]=expf(S[n8][1]-mn0);
            S[n8][2]=expf(S[n8][2]-mn1); S[n8][3]=expf(S[n8][3]-mn1);
            rs0+=S[n8][0]+S[n8][1]; rs1+=S[n8][2]+S[n8][3];
        }
        rs0+=__shfl_xor_sync(~0u,rs0,1); rs0+=__shfl_xor_sync(~0u,rs0,2);
        rs1+=__shfl_xor_sync(~0u,rs1,1); rs1+=__shfl_xor_sync(~0u,rs1,2);
        l0=l0*f0+rs0; l1=l1*f1+rs1;
#pragma unroll
        for(int n8=0;n8<8;n8++){
            O[n8][0]*=f0; O[n8][1]*=f0; O[n8][2]*=f1; O[n8][3]*=f1;
        }
#pragma unroll
        for(int j=0;j<4;j++){
            float p00=S[2*j][0], p01=S[2*j][1], p02=S[2*j][2], p03=S[2*j][3];
            float p10=S[2*j+1][0], p11=S[2*j+1][1], p12=S[2*j+1][2], p13=S[2*j+1][3];
            uint32_t aPh[4], aPl[4];
            aPh[0]=packbf(p00,p01); aPh[1]=packbf(p02,p03);
            aPh[2]=packbf(p10,p11); aPh[3]=packbf(p12,p13);
            {
                __nv_bfloat162 t;
                t=*(__nv_bfloat162*)&aPh[0];
                aPl[0]=packbf(p00-__bfloat162float(t.x), p01-__bfloat162float(t.y));
                t=*(__nv_bfloat162*)&aPh[1];
                aPl[1]=packbf(p02-__bfloat162float(t.x), p03-__bfloat162float(t.y));
                t=*(__nv_bfloat162*)&aPh[2];
                aPl[2]=packbf(p10-__bfloat162float(t.x), p11-__bfloat162float(t.y));
                t=*(__nv_bfloat162*)&aPh[3];
                aPl[3]=packbf(p12-__bfloat162float(t.x), p13-__bfloat162float(t.y));
            }
            uint32_t bHt[4][4], bLt[4][4];
            uint32_t vrow = (j*16 + (lane&15))*FP2 + (lane>>4)*16;
#pragma unroll
            for(int nt=0;nt<4;nt++){
                uint32_t bd = vb + vrow + nt*32;
                ldsm4t(bd, bHt[nt]); ldsm4t(bd+KT2, bLt[nt]);
            }
#pragma unroll
            for(int n8=0;n8<8;n8++){
                uint32_t* bh2=&bHt[n8>>1][(n8&1)*2];
                uint32_t* bl2=&bLt[n8>>1][(n8&1)*2];
                mma16816(O[n8], aPh, bh2);
                mma16816(O[n8], aPh, bl2);
                mma16816(O[n8], aPl, bh2);
            }
        }
        __syncthreads();
    }
    float i0=1.f/l0, i1=1.f/l1;
    int b = bh/HH, h = bh%HH;
#pragma unroll
    for(int n8=0;n8<8;n8++){
        int col = h*64 + n8*8 + t4*2;
#pragma unroll
        for(int hf=0;hf<2;hf++){
            int tokr = b*1024 + tb*128 + w*16 + g + hf*8;
            float v0 = O[n8][hf*2+0]*(hf?i1:i0);
            float v1 = O[n8][hf*2+1]*(hf?i1:i0);
            size_t o=(size_t)tokr*CCH+col;
            bf16 h0=__float2bfloat16(v0), h1=__float2bfloat16(v1);
            __nv_bfloat162 hp2; hp2.x=h0; hp2.y=h1;
            __nv_bfloat162 lp;
            lp.x=__float2bfloat16(v0-__bfloat162float(h0));
            lp.y=__float2bfloat16(v1-__bfloat162float(h1));
            *reinterpret_cast<__nv_bfloat162*>(&g_aoh[o]) = hp2;
            *reinterpret_cast<__nv_bfloat162*>(&g_aol[o]) = lp;
        }
    }
}

// fused dual residual-LN + gated combine
__global__ void k_fin(const float* __restrict__ t3,
                      const float* __restrict__ dg, const float* __restrict__ db_,
                      const float* __restrict__ sg, const float* __restrict__ sb_,
                      float* __restrict__ out){
    int n=blockIdx.x, t=threadIdx.x;
    int s0=g_pos[2*n], s1=g_pos[2*n+1];
    int e0=s0>>13, r0=s0&8191, e1=s1>>13, r1=s1&8191;
    const float* ta = t3 + (size_t)e0*NT*CCH + (size_t)r0*CCH;
    const float* tb = t3 + (size_t)e1*NT*CCH + (size_t)r1*CCH;
    float va[3], vb[3];
    float sa=0.f,qa=0.f,sb2=0.f,qb=0.f;
#pragma unroll
    for(int i=0;i<3;i++){
        int c=t+256*i;
        float h = g_h2[(size_t)n*CCH+c];
        va[i]=h+ta[c]; vb[i]=h+tb[c];
        sa+=va[i]; qa+=va[i]*va[i]; sb2+=vb[i]; qb+=vb[i]*vb[i];
    }
    __shared__ float sh[8][4];
#pragma unroll
    for(int o=16;o;o>>=1){
        sa+=__shfl_xor_sync(~0u,sa,o); qa+=__shfl_xor_sync(~0u,qa,o);
        sb2+=__shfl_xor_sync(~0u,sb2,o); qb+=__shfl_xor_sync(~0u,qb,o);
    }
    if((t&31)==0){ sh[t>>5][0]=sa; sh[t>>5][1]=qa; sh[t>>5][2]=sb2; sh[t>>5][3]=qb; }
    __syncthreads();
    sa=0.f; qa=0.f; sb2=0.f; qb=0.f;
#pragma unroll
    for(int i=0;i<8;i++){ sa+=sh[i][0]; qa+=sh[i][1]; sb2+=sh[i][2]; qb+=sh[i][3]; }
    float ma=sa*(1.f/768.f), ra=rsqrtf(qa*(1.f/768.f)-ma*ma+1e-5f);
    float mb=sb2*(1.f/768.f), rb=rsqrtf(qb*(1.f/768.f)-mb*mb+1e-5f);
    const float* g0p = (e0<2)? dg+e0*CCH : sg+(e0-2)*CCH;
    const float* b0p = (e0<2)? db_+e0*CCH : sb_+(e0-2)*CCH;
    const float* g1p = (e1<2)? dg+e1*CCH : sg+(e1-2)*CCH;
    const float* b1p = (e1<2)? db_+e1*CCH : sb_+(e1-2)*CCH;
    float gw0=g_gw[2*n], gw1=g_gw[2*n+1];
#pragma unroll
    for(int i=0;i<3;i++){
        int c=t+256*i;
        float o0=(va[i]-ma)*ra*g0p[c]+b0p[c];
        float o1=(vb[i]-mb)*rb*g1p[c]+b1p[c];
        out[(size_t)n*CCH+c]=g_x2[(size_t)n*CCH+c]+gw0*o0+gw1*o1;
    }
}

extern "C" void kernel_launch(void* const* d_in, const int* in_sizes, int n_in,
                              void* d_out, int out_size){
    const float *x=(const float*)d_in[0], *rno=(const float*)d_in[1];
    const float *wq=(const float*)d_in[2], *wk=(const float*)d_in[3], *wv=(const float*)d_in[4];
    const float *w_proj=(const float*)d_in[5], *b_proj=(const float*)d_in[6];
    const float *ln1g=(const float*)d_in[7], *ln1b=(const float*)d_in[8];
    const float *ln2g=(const float*)d_in[9], *ln2b=(const float*)d_in[10];
    const float *wr=(const float*)d_in[11], *br=(const float*)d_in[12];
    const float *wn=(const float*)d_in[13], *bn=(const float*)d_in[14];
    const float *temp=(const float*)d_in[15];
    const float *dw1=(const float*)d_in[16], *db1=(const float*)d_in[17];
    const float *dw2=(const float*)d_in[18], *db2=(const float*)d_in[19];
    const float *dw3=(const float*)d_in[20], *db3=(const float*)d_in[21];
    const float *dlng=(const float*)d_in[22], *dlnb=(const float*)d_in[23];
    const float *sw1=(const float*)d_in[24], *sb1=(const float*)d_in[25];
    const float *sw2=(const float*)d_in[26], *sb2=(const float*)d_in[27];
    const float *slng=(const float*)d_in[28], *slnb=(const float*)d_in[29];
    float* out=(float*)d_out;

    static cudaStream_t s2 = nullptr;
    static cudaEvent_t evF = nullptr, evP = nullptr, evE = nullptr, evR = nullptr, evS = nullptr;
    if(!s2){
        cudaStreamCreateWithFlags(&s2, cudaStreamNonBlocking);
        cudaEventCreateWithFlags(&evF, cudaEventDisableTiming);
        cudaEventCreateWithFlags(&evP, cudaEventDisableTiming);
        cudaEventCreateWithFlags(&evE, cudaEventDisableTiming);
        cudaEventCreateWithFlags(&evR, cudaEventDisableTiming);
        cudaEventCreateWithFlags(&evS, cudaEventDisableTiming);
        cudaFuncSetAttribute(k_mma<0>, cudaFuncAttributeMaxDynamicSharedMemorySize, SMEMSZ);
        cudaFuncSetAttribute(k_mma<1>, cudaFuncAttributeMaxDynamicSharedMemorySize, SMEMSZ);
        cudaFuncSetAttribute(k_mmah<2>, cudaFuncAttributeMaxDynamicSharedMemorySize, HSMEM);
        cudaFuncSetAttribute(k_mmah<3>, cudaFuncAttributeMaxDynamicSharedMemorySize, HSMEM);
        cudaFuncSetAttribute(k_flash, cudaFuncAttributeMaxDynamicSharedMemorySize, FSM2);
    }

    bf16 *Bqh,*Bql,*Bph,*Bpl,*h1h,*h1l,*aoh,*aol;
    f16 *Bd1,*Bd2,*Bd3,*Bs1,*Bs2,*h2f,*t1f,*t2f;
    float *x2,*h2,*t3; int *tok,*cnt;
    cudaGetSymbolAddress((void**)&Bqh,g_Bqh); cudaGetSymbolAddress((void**)&Bql,g_Bql);
    cudaGetSymbolAddress((void**)&Bph,g_Bph); cudaGetSymbolAddress((void**)&Bpl,g_Bpl);
    cudaGetSymbolAddress((void**)&Bd1,g_Bd1);
    cudaGetSymbolAddress((void**)&Bd2,g_Bd2);
    cudaGetSymbolAddress((void**)&Bd3,g_Bd3);
    cudaGetSymbolAddress((void**)&Bs1,g_Bs1);
    cudaGetSymbolAddress((void**)&Bs2,g_Bs2);
    cudaGetSymbolAddress((void**)&h1h,g_h1h); cudaGetSymbolAddress((void**)&h1l,g_h1l);
    cudaGetSymbolAddress((void**)&aoh,g_aoh); cudaGetSymbolAddress((void**)&aol,g_aol);
    cudaGetSymbolAddress((void**)&h2f,g_h2f);
    cudaGetSymbolAddress((void**)&t1f,g_t1f); cudaGetSymbolAddress((void**)&t2f,g_t2f);
    cudaGetSymbolAddress((void**)&x2,g_x2); cudaGetSymbolAddress((void**)&h2,g_h2);
    cudaGetSymbolAddress((void**)&t3,g_t3);
    cudaGetSymbolAddress((void**)&tok,g_tok); cudaGetSymbolAddress((void**)&cnt,g_cnt);
    const size_t ZT1=(size_t)NT*FF, ZT3=(size_t)NT*CCH;

    dim3 wb(32,8);
    k_reset<<<1,32>>>();
    // fork: weight prep for proj + experts on s2, overlapped with attention
    cudaEventRecord(evF, 0);
    cudaStreamWaitEvent(s2, evF, 0);
    k_wsplit2<<<dim3(24,12,1),wb,0,s2>>>(w_proj, Bph, Bpl, CCH, CCH);
    cudaEventRecord(evP, s2);
    k_wcvt<<<dim3(96,12,2),wb,0,s2>>>(dw1, Bd1, CCH, FF);
    k_wcvt<<<dim3(96,48,2),wb,0,s2>>>(dw2, Bd2, FF, FF);
    k_wcvt<<<dim3(24,48,2),wb,0,s2>>>(dw3, Bd3, FF, CCH);
    k_wcvt<<<dim3(96,12,6),wb,0,s2>>>(sw1, Bs1, CCH, FF);
    k_wcvt<<<dim3(24,48,6),wb,0,s2>>>(sw2, Bs2, FF, CCH);
    cudaEventRecord(evE, s2);
    // main: QKV weight split + attention
    k_wsplit2<<<dim3(2,12,12),wb>>>(wq, Bqh,           Bql,           CCH, HSZ);
    k_wsplit2<<<dim3(2,12,12),wb>>>(wk, Bqh+CCH*CCH,   Bql+CCH*CCH,   CCH, HSZ);
    k_wsplit2<<<dim3(2,12,12),wb>>>(wv, Bqh+2*CCH*CCH, Bql+2*CCH*CCH, CCH, HSZ);
    k_ln<<<NT,256>>>(x, ln1g, ln1b, nullptr, h1h, h1l, nullptr);
    k_mma<0><<<dim3(18,64),256,SMEMSZ>>>(h1h,h1l,Bqh,Bql,nullptr,nullptr,nullptr,
                                         NT,3*CCH,CCH);
    k_flash<<<dim3(8,BH),256,FSM2>>>();
    cudaStreamWaitEvent(0, evP, 0);
    k_mma<1><<<dim3(6,64),256,SMEMSZ>>>(aoh,aol,Bph,Bpl,b_proj,x,x2, NT,CCH,CCH);
    // fused LN2 + router
    k_lnrouter<<<NT,256>>>(x2, ln2g, ln2b, wr, br, wn, bn, temp, rno);
    cudaEventRecord(evR, 0);
    cudaStreamWaitEvent(0, evE, 0);
    // fork experts: s2 runs L1-simple (z=2..7), main runs L1-deep -> L2-deep
    cudaStreamWaitEvent(s2, evR, 0);
    cudaStreamWaitEvent(s2, evE, 0);
    k_mmah<2><<<dim3(24,64,6),256,HSMEM,s2>>>(h2f,0, nullptr,0, 99, 2,
        Bd1, Bs1,(size_t)CCH*FF, 2, db1,sb1,
        nullptr, t1f, ZT1, NT,FF,CCH, tok, cnt);
    cudaEventRecord(evS, s2);
    k_mmah<2><<<dim3(24,64,2),256,HSMEM>>>(h2f,0, nullptr,0, 99, 0,
        Bd1, Bs1,(size_t)CCH*FF, 2, db1,sb1,
        nullptr, t1f, ZT1, NT,FF,CCH, tok, cnt);
    k_mmah<2><<<dim3(24,64,2),256,HSMEM>>>(t1f,ZT1, nullptr,0, 99, 0,
        Bd2, nullptr,(size_t)FF*FF, 99, db2,nullptr,
        nullptr, t2f, ZT1, NT,FF,FF, nullptr, cnt);
    cudaStreamWaitEvent(0, evS, 0);
    k_mmah<3><<<dim3(6,64,8),256,HSMEM>>>(t2f,ZT1, t1f,ZT1, 2, 0,
        Bd3, Bs2,(size_t)CCH*FF, 2, db3,sb2,
        t3, nullptr, ZT3, NT,CCH,FF, nullptr, cnt);
    k_fin<<<NT,256>>>(t3, dlng, dlnb, slng, slnb, out);
}

// round 16
// speedup vs baseline: 1.0034x; 1.0034x over previous
#include <cuda_runtime.h>
#include <cuda_bf16.h>
#include <cuda_fp16.h>
#include <stdint.h>
#include <math.h>

#define BN 8
#define TT 1024
#define CCH 768
#define HH 12
#define HSZ 64
#define EE 8
#define FF 3072
#define NT (BN*TT)
#define BH (BN*HH)
typedef __nv_bfloat16 bf16;
typedef __half f16;

// ---- static scratch ----
__device__ bf16  g_qh[BH*TT*HSZ], g_ql[BH*TT*HSZ];
__device__ bf16  g_kh[BH*TT*HSZ], g_kl[BH*TT*HSZ];
__device__ bf16  g_vh[BH*TT*HSZ], g_vl[BH*TT*HSZ];
__device__ bf16  g_h1h[NT*CCH], g_h1l[NT*CCH];
__device__ bf16  g_aoh[NT*CCH], g_aol[NT*CCH];
__device__ float g_x2[NT*CCH];
__device__ float g_h2[NT*CCH];
__device__ f16   g_h2f[NT*CCH];
__device__ float g_gw[NT*2];
__device__ int   g_pos[NT*2];
__device__ int   g_tok[EE*NT];
__device__ int   g_cnt[EE];
__device__ f16   g_t1f[(size_t)EE*NT*FF];
__device__ f16   g_t2f[(size_t)2*NT*FF];
__device__ float g_t3[(size_t)EE*NT*CCH];
__device__ bf16  g_Bqh[3*CCH*CCH], g_Bql[3*CCH*CCH];
__device__ bf16  g_Bph[CCH*CCH],  g_Bpl[CCH*CCH];
__device__ f16   g_Bd1[2*CCH*FF];
__device__ f16   g_Bd2[(size_t)2*FF*FF];
__device__ f16   g_Bd3[2*CCH*FF];
__device__ f16   g_Bs1[(size_t)6*CCH*FF];
__device__ f16   g_Bs2[(size_t)6*CCH*FF];

__device__ __forceinline__ float geluf(float v){
    return 0.5f*v*(1.f + erff(v*0.70710678118654752440f));
}
__device__ __forceinline__ uint32_t smem_u32(const void* p){
    uint32_t a;
    asm("{ .reg .u64 t; cvta.to.shared.u64 t, %1; cvt.u32.u64 %0, t; }" : "=r"(a) : "l"(p));
    return a;
}
__device__ __forceinline__ void cp16(uint32_t d, const void* s){
    asm volatile("cp.async.cg.shared.global [%0], [%1], 16;" :: "r"(d), "l"(s));
}
__device__ __forceinline__ void ldsm4(uint32_t a, uint32_t* r){
    asm volatile("ldmatrix.sync.aligned.m8n8.x4.shared.b16 {%0,%1,%2,%3}, [%4];"
        : "=r"(r[0]),"=r"(r[1]),"=r"(r[2]),"=r"(r[3]) : "r"(a));
}
__device__ __forceinline__ void ldsm4t(uint32_t a, uint32_t* r){
    asm volatile("ldmatrix.sync.aligned.m8n8.x4.trans.shared.b16 {%0,%1,%2,%3}, [%4];"
        : "=r"(r[0]),"=r"(r[1]),"=r"(r[2]),"=r"(r[3]) : "r"(a));
}
__device__ __forceinline__ void mma16816(float* c, const uint32_t* a, const uint32_t* b){
    asm volatile("mma.sync.aligned.m16n8k16.row.col.f32.bf16.bf16.f32 "
        "{%0,%1,%2,%3},{%4,%5,%6,%7},{%8,%9},{%0,%1,%2,%3};"
        : "+f"(c[0]),"+f"(c[1]),"+f"(c[2]),"+f"(c[3])
        : "r"(a[0]),"r"(a[1]),"r"(a[2]),"r"(a[3]), "r"(b[0]),"r"(b[1]));
}
__device__ __forceinline__ void mmah16816(float* c, const uint32_t* a, const uint32_t* b){
    asm volatile("mma.sync.aligned.m16n8k16.row.col.f32.f16.f16.f32 "
        "{%0,%1,%2,%3},{%4,%5,%6,%7},{%8,%9},{%0,%1,%2,%3};"
        : "+f"(c[0]),"+f"(c[1]),"+f"(c[2]),"+f"(c[3])
        : "r"(a[0]),"r"(a[1]),"r"(a[2]),"r"(a[3]), "r"(b[0]),"r"(b[1]));
}
__device__ __forceinline__ uint32_t packbf(float a, float b){
    __nv_bfloat162 p; p.x=__float2bfloat16(a); p.y=__float2bfloat16(b);
    return *reinterpret_cast<uint32_t*>(&p);
}

__global__ void k_reset(){ if(threadIdx.x < EE) g_cnt[threadIdx.x] = 0; }

// W[K][N] -> out[N][K] hi/lo bf16 (attention weights)
__global__ void k_wsplit2(const float* __restrict__ W, bf16* __restrict__ oh,
                          bf16* __restrict__ ol, int K, int N){
    int e = blockIdx.z;
    W += (size_t)e*K*N; oh += (size_t)e*K*N; ol += (size_t)e*K*N;
    __shared__ float s[64][33];
    int n0 = blockIdx.x*32, k0 = blockIdx.y*64;
    int tx = threadIdx.x, ty = threadIdx.y;
#pragma unroll
    for(int r=0;r<8;r++){ int kk=ty+r*8; s[kk][tx] = W[(size_t)(k0+kk)*N + n0+tx]; }
    __syncthreads();
#pragma unroll
    for(int r=0;r<4;r++){
        int n = ty + r*8;
        float v0 = s[2*tx][n], v1 = s[2*tx+1][n];
        bf16 h0 = __float2bfloat16(v0), h1 = __float2bfloat16(v1);
        bf16 hh[2] = {h0, h1};
        bf16 ll[2] = {__float2bfloat16(v0-__bfloat162float(h0)),
                      __float2bfloat16(v1-__bfloat162float(h1))};
        size_t o = (size_t)(n0+n)*K + k0 + 2*tx;
        *reinterpret_cast<uint32_t*>(&oh[o]) = *reinterpret_cast<uint32_t*>(hh);
        *reinterpret_cast<uint32_t*>(&ol[o]) = *reinterpret_cast<uint32_t*>(ll);
    }
}

// W[K][N] -> out[N][K] single fp16 (expert weights)
__global__ void k_wcvt(const float* __restrict__ W, f16* __restrict__ oh, int K, int N){
    int e = blockIdx.z;
    W += (size_t)e*K*N; oh += (size_t)e*K*N;
    __shared__ float s[64][33];
    int n0 = blockIdx.x*32, k0 = blockIdx.y*64;
    int tx = threadIdx.x, ty = threadIdx.y;
#pragma unroll
    for(int r=0;r<8;r++){ int kk=ty+r*8; s[kk][tx] = W[(size_t)(k0+kk)*N + n0+tx]; }
    __syncthreads();
#pragma unroll
    for(int r=0;r<4;r++){
        int n = ty + r*8;
        __half2 hp; hp.x=__float2half(s[2*tx][n]); hp.y=__float2half(s[2*tx+1][n]);
        size_t o = (size_t)(n0+n)*K + k0 + 2*tx;
        *reinterpret_cast<__half2*>(&oh[o]) = hp;
    }
}

__global__ void k_ln(const float* __restrict__ in, const float* __restrict__ gam,
                     const float* __restrict__ bet, float* __restrict__ out,
                     bf16* __restrict__ oh, bf16* __restrict__ ol, f16* __restrict__ of){
    int n = blockIdx.x, t = threadIdx.x;
    const float* row = in + (size_t)n*CCH;
    float v[3], s=0.f, s2=0.f;
#pragma unroll
    for(int i=0;i<3;i++){ v[i]=row[t+256*i]; s+=v[i]; s2+=v[i]*v[i]; }
    __shared__ float shs[8], shq[8];
#pragma unroll
    for(int o=16;o;o>>=1){ s+=__shfl_xor_sync(~0u,s,o); s2+=__shfl_xor_sync(~0u,s2,o); }
    if((t&31)==0){ shs[t>>5]=s; shq[t>>5]=s2; }
    __syncthreads();
    s=0.f; s2=0.f;
#pragma unroll
    for(int i=0;i<8;i++){ s+=shs[i]; s2+=shq[i]; }
    float mean=s*(1.f/768.f), var=s2*(1.f/768.f)-mean*mean, r=rsqrtf(var+1e-5f);
#pragma unroll
    for(int i=0;i<3;i++){
        int c=t+256*i;
        float o=(v[i]-mean)*r*gam[c]+bet[c];
        if(out) out[(size_t)n*CCH+c]=o;
        if(oh){
            bf16 hi=__float2bfloat16(o);
            oh[(size_t)n*CCH+c]=hi;
            ol[(size_t)n*CCH+c]=__float2bfloat16(o-__bfloat162float(hi));
        }
        if(of) of[(size_t)n*CCH+c]=__float2half(o);
    }
}

// fused LN2 + noisy top-2 router (block per token)
__global__ void k_lnrouter(const float* __restrict__ gam, const float* __restrict__ bet,
                           const float* __restrict__ wr, const float* __restrict__ br,
                           const float* __restrict__ wn, const float* __restrict__ bnn,
                           const float* __restrict__ temp, const float* __restrict__ noise){
    int n = blockIdx.x, t = threadIdx.x, lane = t&31, warp = t>>5;
    const float* row = g_x2 + (size_t)n*CCH;
    float v[3], s=0.f, s2=0.f;
#pragma unroll
    for(int i=0;i<3;i++){ v[i]=row[t+256*i]; s+=v[i]; s2+=v[i]*v[i]; }
    __shared__ float shs[8], shq[8];
#pragma unroll
    for(int o=16;o;o>>=1){ s+=__shfl_xor_sync(~0u,s,o); s2+=__shfl_xor_sync(~0u,s2,o); }
    if(lane==0){ shs[warp]=s; shq[warp]=s2; }
    __syncthreads();
    s=0.f; s2=0.f;
#pragma unroll
    for(int i=0;i<8;i++){ s+=shs[i]; s2+=shq[i]; }
    float mean=s*(1.f/768.f), var=s2*(1.f/768.f)-mean*mean, r=rsqrtf(var+1e-5f);
    float acc[16];
#pragma unroll
    for(int j=0;j<16;j++) acc[j]=0.f;
#pragma unroll
    for(int i=0;i<3;i++){
        int c=t+256*i;
        float o=(v[i]-mean)*r*gam[c]+bet[c];
        g_h2[(size_t)n*CCH+c]=o;
        g_h2f[(size_t)n*CCH+c]=__float2half(o);
        const float* wrp=wr+c*EE; const float* wnp=wn+c*EE;
#pragma unroll
        for(int e=0;e<8;e++){ acc[e]+=o*wrp[e]; acc[8+e]+=o*wnp[e]; }
    }
#pragma unroll
    for(int o=16;o;o>>=1)
#pragma unroll
        for(int j=0;j<16;j++) acc[j]+=__shfl_xor_sync(~0u,acc[j],o);
    __shared__ float sh2[8][16];
    if(lane==0)
#pragma unroll
        for(int j=0;j<16;j++) sh2[warp][j]=acc[j];
    __syncthreads();
    if(t==0){
        float ny[8];
#pragma unroll
        for(int e=0;e<8;e++){
            float rr=0.f, qq=0.f;
#pragma unroll
            for(int w2=0;w2<8;w2++){ rr+=sh2[w2][e]; qq+=sh2[w2][8+e]; }
            float tc=fminf(fmaxf(temp[0],0.5f),2.0f);
            float z=qq+bnn[e];
            float sp=(z>20.f)? z : log1pf(expf(z));
            ny[e]=rr+br[e] + tc*noise[(size_t)n*EE+e]*sp;
        }
        int i1=0;
#pragma unroll
        for(int e=1;e<8;e++) if(ny[e]>ny[i1]) i1=e;
        int i2=-1;
#pragma unroll
        for(int e=0;e<8;e++){ if(e==i1) continue; if(i2<0||ny[e]>ny[i2]) i2=e; }
        float e2=expf(ny[i2]-ny[i1]);
        float gv[2]={1.f/(1.f+e2), e2/(1.f+e2)};
        int id[2]={i1,i2};
#pragma unroll
        for(int k2=0;k2<2;k2++){
            int e=id[k2];
            int rw=atomicAdd(&g_cnt[e],1);
            g_tok[e*NT+rw]=n;
            g_pos[n*2+k2]=e*NT+rw;
            g_gw[n*2+k2]=gv[k2];
        }
    }
}

// ---- bf16 3-product GEMM (QKV + proj), 2-stage, 2 CTAs/SM ----
#define PITCH 80
#define TILEB 10240
#define STAGEB 40960
#define SMEMSZ (2*STAGEB)
template<int EPI>
__global__ void __launch_bounds__(256,2)
k_mma(const bf16* __restrict__ Ah, const bf16* __restrict__ Al,
      const bf16* __restrict__ Bh, const bf16* __restrict__ Bl,
      const float* __restrict__ bias, const float* __restrict__ resid,
      float* __restrict__ out32, int M, int Nn, int K){
    int by = blockIdx.y, bx = blockIdx.x;
    extern __shared__ char smem[];
    uint32_t su = smem_u32(smem);
    int tid=threadIdx.x, lane=tid&31, wid=tid>>5;
    int wm=wid&3, wn=wid>>2;
    const int KT = K/32;
    float acc[2][8][4];
#pragma unroll
    for(int a=0;a<2;a++)
#pragma unroll
        for(int b=0;b<8;b++)
#pragma unroll
            for(int c=0;c<4;c++) acc[a][b][c]=0.f;
    auto load_stage = [&](int kt){
        uint32_t sb = su + (kt&1)*STAGEB;
#pragma unroll
        for(int i=0;i<8;i++){
            int c = tid + i*256;
            int tile=c>>9, w=c&511, row=w>>2, q=w&3;
            uint32_t d = sb + tile*TILEB + row*PITCH + q*16;
            const bf16* src;
            if(tile<2) src = (tile==0?Ah:Al) + (size_t)(by*128+row)*K + kt*32 + q*8;
            else       src = (tile==2?Bh:Bl) + (size_t)(bx*128+row)*K + kt*32 + q*8;
            cp16(d, src);
        }
        asm volatile("cp.async.commit_group;" ::: "memory");
    };
    load_stage(0);
    for(int kt=0; kt<KT; kt++){
        if(kt+1<KT){
            load_stage(kt+1);
            asm volatile("cp.async.wait_group 1;" ::: "memory");
        } else {
            asm volatile("cp.async.wait_group 0;" ::: "memory");
        }
        __syncthreads();
        uint32_t sb = su + (kt&1)*STAGEB;
#pragma unroll
        for(int kh=0; kh<2; kh++){
            uint32_t aH[2][4], aL[2][4];
            int arow = wm*32 + (lane&15);
            uint32_t ako = kh*32 + (lane>>4)*16;
#pragma unroll
            for(int mt=0;mt<2;mt++){
                uint32_t ad = sb + (arow+mt*16)*PITCH + ako;
                ldsm4(ad, aH[mt]); ldsm4(ad + TILEB, aL[mt]);
            }
            uint32_t bHf[4][4], bLf[4][4];
            int brow = wn*64 + ((lane&7) | ((lane&16)>>1));
            uint32_t bko = kh*32 + ((lane>>3)&1)*16;
#pragma unroll
            for(int nt=0;nt<4;nt++){
                uint32_t bd = sb + 2*TILEB + (brow+nt*16)*PITCH + bko;
                ldsm4(bd, bHf[nt]); ldsm4(bd + TILEB, bLf[nt]);
            }
#pragma unroll
            for(int mt=0;mt<2;mt++)
#pragma unroll
            for(int n8=0;n8<8;n8++){
                uint32_t* bh = &bHf[n8>>1][(n8&1)*2];
                uint32_t* bl = &bLf[n8>>1][(n8&1)*2];
                mma16816(acc[mt][n8], aH[mt], bh);
                mma16816(acc[mt][n8], aH[mt], bl);
                mma16816(acc[mt][n8], aL[mt], bh);
            }
        }
        __syncthreads();
    }
    int g = lane>>2, t4 = lane&3;
#pragma unroll
    for(int mt=0;mt<2;mt++)
#pragma unroll
    for(int n8=0;n8<8;n8++){
        int col = bx*128 + wn*64 + n8*8 + t4*2;
#pragma unroll
        for(int hf=0; hf<2; hf++){
            int row = by*128 + wm*32 + mt*16 + g + hf*8;
            float v0 = acc[mt][n8][hf*2+0];
            float v1 = acc[mt][n8][hf*2+1];
            if(EPI==0){
                int which = col/CCH, rem = col - which*CCH;
                int h = rem>>6, d0 = rem&63;
                int b = row>>10, t = row&1023;
                size_t o = ((size_t)(b*HH+h)*TT + t)*HSZ + d0;
                bf16* dh = which==0? g_qh : which==1? g_kh : g_vh;
                bf16* dl = which==0? g_ql : which==1? g_kl : g_vl;
                bf16 h0=__float2bfloat16(v0), h1=__float2bfloat16(v1);
                __nv_bfloat162 hp; hp.x=h0; hp.y=h1;
                __nv_bfloat162 lp;
                lp.x=__float2bfloat16(v0-__bfloat162float(h0));
                lp.y=__float2bfloat16(v1-__bfloat162float(h1));
                *reinterpret_cast<__nv_bfloat162*>(&dh[o]) = hp;
                *reinterpret_cast<__nv_bfloat162*>(&dl[o]) = lp;
            } else {
                size_t o=(size_t)row*Nn+col;
                out32[o]   = v0 + bias[col]   + resid[o];
                out32[o+1] = v1 + bias[col+1] + resid[o+1];
            }
        }
    }
}

// ---- fp16 single-product GEMM (experts), 3-stage, 2 CTAs/SM, z-batched ----
#define HSTG (2*TILEB)
#define HSMEM (3*HSTG)
template<int EPI>
__global__ void __launch_bounds__(256,2)
k_mmah(const f16* __restrict__ A1, size_t zsA, const f16* __restrict__ A2, size_t zsA2,
       int zSplitA,
       const f16* __restrict__ B1, const f16* __restrict__ B2, size_t zsB, int zSplit,
       const float* __restrict__ b1, const float* __restrict__ b2,
       float* __restrict__ out32, f16* __restrict__ outH, size_t zsOut,
       int M, int Nn, int K,
       const int* __restrict__ tok, const int* __restrict__ cnt){
    int z = blockIdx.z;
    if(cnt) M = cnt[z];
    int by = blockIdx.y, bx = blockIdx.x;
    if(by*128 >= M) return;
    const f16* A = (z < zSplitA) ? A1 + (size_t)z*zsA : A2 + (size_t)z*zsA2;
    const f16* Bp; const float* bias;
    if(z < zSplit){ Bp=B1+(size_t)z*zsB; bias=b1+(size_t)z*Nn; }
    else { Bp=B2+(size_t)(z-zSplit)*zsB; bias=b2+(size_t)(z-zSplit)*Nn; }
    if(out32) out32 += (size_t)z*zsOut;
    if(outH)  outH  += (size_t)z*zsOut;
    if(tok) tok += (size_t)z*NT;
    extern __shared__ char smem[];
    uint32_t su = smem_u32(smem);
    int tid=threadIdx.x, lane=tid&31, wid=tid>>5;
    int wm=wid&3, wn=wid>>2;
    const int KT = K/32;
    float acc[2][8][4];
#pragma unroll
    for(int a=0;a<2;a++)
#pragma unroll
        for(int b=0;b<8;b++)
#pragma unroll
            for(int c=0;c<4;c++) acc[a][b][c]=0.f;
    auto load_stage = [&](int kt){
        uint32_t sb = su + (kt%3)*HSTG;
#pragma unroll
        for(int i=0;i<4;i++){
            int c = tid + i*256;
            int tile=c>>9, w=c&511, row=w>>2, q=w&3;
            uint32_t d = sb + tile*TILEB + row*PITCH + q*16;
            const f16* src;
            if(tile==0){
                int rg=by*128+row; if(rg>=M) rg=M-1;
                int asrc = tok ? tok[rg] : rg;
                src = A + (size_t)asrc*K + kt*32 + q*8;
            } else {
                src = Bp + (size_t)(bx*128+row)*K + kt*32 + q*8;
            }
            cp16(d, src);
        }
        asm volatile("cp.async.commit_group;" ::: "memory");
    };
    load_stage(0);
    if(KT>1) load_stage(1);
    for(int kt=0; kt<KT; kt++){
        if(kt+2<KT) load_stage(kt+2);
        if(kt+2<KT)      asm volatile("cp.async.wait_group 2;" ::: "memory");
        else if(kt+1<KT) asm volatile("cp.async.wait_group 1;" ::: "memory");
        else             asm volatile("cp.async.wait_group 0;" ::: "memory");
        __syncthreads();
        uint32_t sb = su + (kt%3)*HSTG;
#pragma unroll
        for(int kh=0; kh<2; kh++){
            uint32_t aF[2][4];
            int arow = wm*32 + (lane&15);
            uint32_t ako = kh*32 + (lane>>4)*16;
#pragma unroll
            for(int mt=0;mt<2;mt++)
                ldsm4(sb + (arow+mt*16)*PITCH + ako, aF[mt]);
            uint32_t bF[4][4];
            int brow = wn*64 + ((lane&7) | ((lane&16)>>1));
            uint32_t bko = kh*32 + ((lane>>3)&1)*16;
#pragma unroll
            for(int nt=0;nt<4;nt++)
                ldsm4(sb + TILEB + (brow+nt*16)*PITCH + bko, bF[nt]);
#pragma unroll
            for(int mt=0;mt<2;mt++)
#pragma unroll
            for(int n8=0;n8<8;n8++)
                mmah16816(acc[mt][n8], aF[mt], &bF[n8>>1][(n8&1)*2]);
        }
        __syncthreads();
    }
    int g = lane>>2, t4 = lane&3;
#pragma unroll
    for(int mt=0;mt<2;mt++)
#pragma unroll
    for(int n8=0;n8<8;n8++){
        int col = bx*128 + wn*64 + n8*8 + t4*2;
#pragma unroll
        for(int hf=0; hf<2; hf++){
            int row = by*128 + wm*32 + mt*16 + g + hf*8;
            if(row >= M) continue;
            float v0 = acc[mt][n8][hf*2+0];
            float v1 = acc[mt][n8][hf*2+1];
            size_t o=(size_t)row*Nn+col;
            if(EPI==2){
                __half2 hp;
                hp.x = __float2half(geluf(v0 + bias[col]));
                hp.y = __float2half(geluf(v1 + bias[col+1]));
                *reinterpret_cast<__half2*>(&outH[o]) = hp;
            } else {
                out32[o]   = v0 + bias[col];
                out32[o+1] = v1 + bias[col+1];
            }
        }
    }
}

// ---- flash attention v2 ----
#define FP2 144
#define QT (128*FP2)
#define KT2 (64*FP2)
#define STG2 (4*KT2)
#define FSM2 (2*QT + 2*STG2)
__global__ void __launch_bounds__(256,1) k_flash(){
    int tb = 7 - blockIdx.x, bh = blockIdx.y;
    extern __shared__ char fsm[];
    uint32_t su = smem_u32(fsm);
    uint32_t qb = su, kvb = su + 2*QT;
    int tid=threadIdx.x, lane=tid&31, w=tid>>5;
    const size_t hb = (size_t)bh*TT*HSZ;
#pragma unroll
    for(int i=0;i<8;i++){
        int c = tid + i*256;
        int half = c>>10, w2 = c&1023, row = w2>>3, q = w2&7;
        cp16(qb + half*QT + row*FP2 + q*16,
             (half? g_ql : g_qh) + hb + (size_t)(tb*128+row)*HSZ + q*8);
    }
    auto loadKV = [&](int sb){
        uint32_t base = kvb + (sb&1)*STG2;
#pragma unroll
        for(int i=0;i<8;i++){
            int c = tid + i*256;
            int arr = c>>9, w2 = c&511, row = w2>>3, q = w2&7;
            const bf16* src = (arr==0? g_kh : arr==1? g_kl : arr==2? g_vh : g_vl)
                            + hb + (size_t)(sb*64+row)*HSZ + q*8;
            cp16(base + arr*KT2 + row*FP2 + q*16, src);
        }
        asm volatile("cp.async.commit_group;" ::: "memory");
    };
    loadKV(0);
    float m0=-1e30f, m1=-1e30f, l0=0.f, l1=0.f;
    float O[8][4];
#pragma unroll
    for(int n8=0;n8<8;n8++)
#pragma unroll
        for(int c=0;c<4;c++) O[n8][c]=0.f;
    const float scale=0.036084391824351615f;
    int brow = (lane&7) | ((lane&16)>>1);
    int t4 = lane&3, g = lane>>2;
    int smax = 2*tb+1;
    for(int sb=0; sb<=smax; sb++){
        if(sb<smax) loadKV(sb+1);
        if(sb<smax) asm volatile("cp.async.wait_group 1;" ::: "memory");
        else        asm volatile("cp.async.wait_group 0;" ::: "memory");
        __syncthreads();
        uint32_t kb = kvb + (sb&1)*STG2;
        uint32_t vb = kb + 2*KT2;
        float S[8][4];
#pragma unroll
        for(int n8=0;n8<8;n8++)
#pragma unroll
            for(int c=0;c<4;c++) S[n8][c]=0.f;
#pragma unroll
        for(int kc=0;kc<4;kc++){
            uint32_t aH[4], aL[4];
            uint32_t ad = qb + (w*16+(lane&15))*FP2 + kc*32 + (lane>>4)*16;
            ldsm4(ad, aH); ldsm4(ad+QT, aL);
            uint32_t bHt[4][4], bLt[4][4];
#pragma unroll
            for(int nt=0;nt<4;nt++){
                uint32_t bd = kb + (nt*16+brow)*FP2 + kc*32 + ((lane>>3)&1)*16;
                ldsm4(bd, bHt[nt]); ldsm4(bd+KT2, bLt[nt]);
            }
#pragma unroll
            for(int n8=0;n8<8;n8++){
                uint32_t* bh2=&bHt[n8>>1][(n8&1)*2];
                uint32_t* bl2=&bLt[n8>>1][(n8&1)*2];
                mma16816(S[n8], aH, bh2);
                mma16816(S[n8], aH, bl2);
                mma16816(S[n8], aL, bh2);
            }
        }
        int rg0 = tb*128 + w*16 + g;
#pragma unroll
        for(int n8=0;n8<8;n8++)
#pragma unroll
            for(int c=0;c<4;c++){
                S[n8][c] *= scale;
                if(sb >= 2*tb){
                    int sg = sb*64 + n8*8 + t4*2 + (c&1);
                    int rg = rg0 + ((c>=2)?8:0);
                    if(sg > rg) S[n8][c] = -1e30f;
                }
            }
        float mx0=-1e30f, mx1=-1e30f;
#pragma unroll
        for(int n8=0;n8<8;n8++){
            mx0=fmaxf(mx0,fmaxf(S[n8][0],S[n8][1]));
            mx1=fmaxf(mx1,fmaxf(S[n8][2],S[n8][3]));
        }
        mx0=fmaxf(mx0,__shfl_xor_sync(~0u,mx0,1)); mx0=fmaxf(mx0,__shfl_xor_sync(~0u,mx0,2));
        mx1=fmaxf(mx1,__shfl_xor_sync(~0u,mx1,1)); mx1=fmaxf(mx1,__shfl_xor_sync(~0u,mx1,2));
        float mn0=fmaxf(m0,mx0), mn1=fmaxf(m1,mx1);
        float f0=expf(m0-mn0), f1=expf(m1-mn1);
        m0=mn0; m1=mn1;
        float rs0=0.f, rs1=0.f;
#pragma unroll
        for(int n8=0;n8<8;n8++){
            S[n8][0]=expf(S[n8][0]-mn0); S[n8][1]=expf(S[n8][1]-mn0);
            S[n8][2]=expf(S[n8][2]-mn1); S[n8][3]=expf(S[n8][3]-mn1);
            rs0+=S[n8][0]+S[n8][1]; rs1+=S[n8][2]+S[n8][3];
        }
        rs0+=__shfl_xor_sync(~0u,rs0,1); rs0+=__shfl_xor_sync(~0u,rs0,2);
        rs1+=__shfl_xor_sync(~0u,rs1,1); rs1+=__shfl_xor_sync(~0u,rs1,2);
        l0=l0*f0+rs0; l1=l1*f1+rs1;
#pragma unroll
        for(int n8=0;n8<8;n8++){
            O[n8][0]*=f0; O[n8][1]*=f0; O[n8][2]*=f1; O[n8][3]*=f1;
        }
#pragma unroll
        for(int j=0;j<4;j++){
            float p00=S[2*j][0], p01=S[2*j][1], p02=S[2*j][2], p03=S[2*j][3];
            float p10=S[2*j+1][0], p11=S[2*j+1][1], p12=S[2*j+1][2], p13=S[2*j+1][3];
            uint32_t aPh[4], aPl[4];
            aPh[0]=packbf(p00,p01); aPh[1]=packbf(p02,p03);
            aPh[2]=packbf(p10,p11); aPh[3]=packbf(p12,p13);
            {
                __nv_bfloat162 t;
                t=*(__nv_bfloat162*)&aPh[0];
                aPl[0]=packbf(p00-__bfloat162float(t.x), p01-__bfloat162float(t.y));
                t=*(__nv_bfloat162*)&aPh[1];
                aPl[1]=packbf(p02-__bfloat162float(t.x), p03-__bfloat162float(t.y));
                t=*(__nv_bfloat162*)&aPh[2];
                aPl[2]=packbf(p10-__bfloat162float(t.x), p11-__bfloat162float(t.y));
                t=*(__nv_bfloat162*)&aPh[3];
                aPl[3]=packbf(p12-__bfloat162float(t.x), p13-__bfloat162float(t.y));
            }
            uint32_t bHt[4][4], bLt[4][4];
            uint32_t vrow = (j*16 + (lane&15))*FP2 + (lane>>4)*16;
#pragma unroll
            for(int nt=0;nt<4;nt++){
                uint32_t bd = vb + vrow + nt*32;
                ldsm4t(bd, bHt[nt]); ldsm4t(bd+KT2, bLt[nt]);
            }
#pragma unroll
            for(int n8=0;n8<8;n8++){
                uint32_t* bh2=&bHt[n8>>1][(n8&1)*2];
                uint32_t* bl2=&bLt[n8>>1][(n8&1)*2];
                mma16816(O[n8], aPh, bh2);
                mma16816(O[n8], aPh, bl2);
                mma16816(O[n8], aPl, bh2);
            }
        }
        __syncthreads();
    }
    float i0=1.f/l0, i1=1.f/l1;
    int b = bh/HH, h = bh%HH;
#pragma unroll
    for(int n8=0;n8<8;n8++){
        int col = h*64 + n8*8 + t4*2;
#pragma unroll
        for(int hf=0;hf<2;hf++){
            int tokr = b*1024 + tb*128 + w*16 + g + hf*8;
            float v0 = O[n8][hf*2+0]*(hf?i1:i0);
            float v1 = O[n8][hf*2+1]*(hf?i1:i0);
            size_t o=(size_t)tokr*CCH+col;
            bf16 h0=__float2bfloat16(v0), h1=__float2bfloat16(v1);
            __nv_bfloat162 hp2; hp2.x=h0; hp2.y=h1;
            __nv_bfloat162 lp;
            lp.x=__float2bfloat16(v0-__bfloat162float(h0));
            lp.y=__float2bfloat16(v1-__bfloat162float(h1));
            *reinterpret_cast<__nv_bfloat162*>(&g_aoh[o]) = hp2;
            *reinterpret_cast<__nv_bfloat162*>(&g_aol[o]) = lp;
        }
    }
}

// fused dual residual-LN + gated combine
__global__ void k_fin(const float* __restrict__ t3,
                      const float* __restrict__ dg, const float* __restrict__ db_,
                      const float* __restrict__ sg, const float* __restrict__ sb_,
                      float* __restrict__ out){
    int n=blockIdx.x, t=threadIdx.x;
    int s0=g_pos[2*n], s1=g_pos[2*n+1];
    int e0=s0>>13, r0=s0&8191, e1=s1>>13, r1=s1&8191;
    const float* ta = t3 + (size_t)e0*NT*CCH + (size_t)r0*CCH;
    const float* tb = t3 + (size_t)e1*NT*CCH + (size_t)r1*CCH;
    float va[3], vb[3];
    float sa=0.f,qa=0.f,sb2=0.f,qb=0.f;
#pragma unroll
    for(int i=0;i<3;i++){
        int c=t+256*i;
        float h = g_h2[(size_t)n*CCH+c];
        va[i]=h+ta[c]; vb[i]=h+tb[c];
        sa+=va[i]; qa+=va[i]*va[i]; sb2+=vb[i]; qb+=vb[i]*vb[i];
    }
    __shared__ float sh[8][4];
#pragma unroll
    for(int o=16;o;o>>=1){
        sa+=__shfl_xor_sync(~0u,sa,o); qa+=__shfl_xor_sync(~0u,qa,o);
        sb2+=__shfl_xor_sync(~0u,sb2,o); qb+=__shfl_xor_sync(~0u,qb,o);
    }
    if((t&31)==0){ sh[t>>5][0]=sa; sh[t>>5][1]=qa; sh[t>>5][2]=sb2; sh[t>>5][3]=qb; }
    __syncthreads();
    sa=0.f; qa=0.f; sb2=0.f; qb=0.f;
#pragma unroll
    for(int i=0;i<8;i++){ sa+=sh[i][0]; qa+=sh[i][1]; sb2+=sh[i][2]; qb+=sh[i][3]; }
    float ma=sa*(1.f/768.f), ra=rsqrtf(qa*(1.f/768.f)-ma*ma+1e-5f);
    float mb=sb2*(1.f/768.f), rb=rsqrtf(qb*(1.f/768.f)-mb*mb+1e-5f);
    const float* g0p = (e0<2)? dg+e0*CCH : sg+(e0-2)*CCH;
    const float* b0p = (e0<2)? db_+e0*CCH : sb_+(e0-2)*CCH;
    const float* g1p = (e1<2)? dg+e1*CCH : sg+(e1-2)*CCH;
    const float* b1p = (e1<2)? db_+e1*CCH : sb_+(e1-2)*CCH;
    float gw0=g_gw[2*n], gw1=g_gw[2*n+1];
#pragma unroll
    for(int i=0;i<3;i++){
        int c=t+256*i;
        float o0=(va[i]-ma)*ra*g0p[c]+b0p[c];
        float o1=(vb[i]-mb)*rb*g1p[c]+b1p[c];
        out[(size_t)n*CCH+c]=g_x2[(size_t)n*CCH+c]+gw0*o0+gw1*o1;
    }
}

extern "C" void kernel_launch(void* const* d_in, const int* in_sizes, int n_in,
                              void* d_out, int out_size){
    const float *x=(const float*)d_in[0], *rno=(const float*)d_in[1];
    const float *wq=(const float*)d_in[2], *wk=(const float*)d_in[3], *wv=(const float*)d_in[4];
    const float *w_proj=(const float*)d_in[5], *b_proj=(const float*)d_in[6];
    const float *ln1g=(const float*)d_in[7], *ln1b=(const float*)d_in[8];
    const float *ln2g=(const float*)d_in[9], *ln2b=(const float*)d_in[10];
    const float *wr=(const float*)d_in[11], *br=(const float*)d_in[12];
    const float *wn=(const float*)d_in[13], *bn=(const float*)d_in[14];
    const float *temp=(const float*)d_in[15];
    const float *dw1=(const float*)d_in[16], *db1=(const float*)d_in[17];
    const float *dw2=(const float*)d_in[18], *db2=(const float*)d_in[19];
    const float *dw3=(const float*)d_in[20], *db3=(const float*)d_in[21];
    const float *dlng=(const float*)d_in[22], *dlnb=(const float*)d_in[23];
    const float *sw1=(const float*)d_in[24], *sb1=(const float*)d_in[25];
    const float *sw2=(const float*)d_in[26], *sb2=(const float*)d_in[27];
    const float *slng=(const float*)d_in[28], *slnb=(const float*)d_in[29];
    float* out=(float*)d_out;

    static cudaStream_t s2 = nullptr;
    static cudaEvent_t evF = nullptr, evP = nullptr, evE = nullptr;
    if(!s2){
        cudaStreamCreateWithFlags(&s2, cudaStreamNonBlocking);
        cudaEventCreateWithFlags(&evF, cudaEventDisableTiming);
        cudaEventCreateWithFlags(&evP, cudaEventDisableTiming);
        cudaEventCreateWithFlags(&evE, cudaEventDisableTiming);
        cudaFuncSetAttribute(k_mma<0>, cudaFuncAttributeMaxDynamicSharedMemorySize, SMEMSZ);
        cudaFuncSetAttribute(k_mma<1>, cudaFuncAttributeMaxDynamicSharedMemorySize, SMEMSZ);
        cudaFuncSetAttribute(k_mmah<2>, cudaFuncAttributeMaxDynamicSharedMemorySize, HSMEM);
        cudaFuncSetAttribute(k_mmah<3>, cudaFuncAttributeMaxDynamicSharedMemorySize, HSMEM);
        cudaFuncSetAttribute(k_flash, cudaFuncAttributeMaxDynamicSharedMemorySize, FSM2);
    }

    bf16 *Bqh,*Bql,*Bph,*Bpl,*h1h,*h1l,*aoh,*aol;
    f16 *Bd1,*Bd2,*Bd3,*Bs1,*Bs2,*h2f,*t1f,*t2f;
    float *x2,*h2,*t3; int *tok,*cnt;
    cudaGetSymbolAddress((void**)&Bqh,g_Bqh); cudaGetSymbolAddress((void**)&Bql,g_Bql);
    cudaGetSymbolAddress((void**)&Bph,g_Bph); cudaGetSymbolAddress((void**)&Bpl,g_Bpl);
    cudaGetSymbolAddress((void**)&Bd1,g_Bd1);
    cudaGetSymbolAddress((void**)&Bd2,g_Bd2);
    cudaGetSymbolAddress((void**)&Bd3,g_Bd3);
    cudaGetSymbolAddress((void**)&Bs1,g_Bs1);
    cudaGetSymbolAddress((void**)&Bs2,g_Bs2);
    cudaGetSymbolAddress((void**)&h1h,g_h1h); cudaGetSymbolAddress((void**)&h1l,g_h1l);
    cudaGetSymbolAddress((void**)&aoh,g_aoh); cudaGetSymbolAddress((void**)&aol,g_aol);
    cudaGetSymbolAddress((void**)&h2f,g_h2f);
    cudaGetSymbolAddress((void**)&t1f,g_t1f); cudaGetSymbolAddress((void**)&t2f,g_t2f);
    cudaGetSymbolAddress((void**)&x2,g_x2); cudaGetSymbolAddress((void**)&h2,g_h2);
    cudaGetSymbolAddress((void**)&t3,g_t3);
    cudaGetSymbolAddress((void**)&tok,g_tok); cudaGetSymbolAddress((void**)&cnt,g_cnt);
    const size_t ZT1=(size_t)NT*FF, ZT3=(size_t)NT*CCH;

    dim3 wb(32,8);
    k_reset<<<1,32>>>();
    // fork: weight prep for proj + experts on s2, overlapped with attention
    cudaEventRecord(evF, 0);
    cudaStreamWaitEvent(s2, evF, 0);
    k_wsplit2<<<dim3(24,12,1),wb,0,s2>>>(w_proj, Bph, Bpl, CCH, CCH);
    cudaEventRecord(evP, s2);
    k_wcvt<<<dim3(96,12,2),wb,0,s2>>>(dw1, Bd1, CCH, FF);
    k_wcvt<<<dim3(96,48,2),wb,0,s2>>>(dw2, Bd2, FF, FF);
    k_wcvt<<<dim3(24,48,2),wb,0,s2>>>(dw3, Bd3, FF, CCH);
    k_wcvt<<<dim3(96,12,6),wb,0,s2>>>(sw1, Bs1, CCH, FF);
    k_wcvt<<<dim3(24,48,6),wb,0,s2>>>(sw2, Bs2, FF, CCH);
    cudaEventRecord(evE, s2);
    // main: QKV weight split + attention
    k_wsplit2<<<dim3(2,12,12),wb>>>(wq, Bqh,           Bql,           CCH, HSZ);
    k_wsplit2<<<dim3(2,12,12),wb>>>(wk, Bqh+CCH*CCH,   Bql+CCH*CCH,   CCH, HSZ);
    k_wsplit2<<<dim3(2,12,12),wb>>>(wv, Bqh+2*CCH*CCH, Bql+2*CCH*CCH, CCH, HSZ);
    k_ln<<<NT,256>>>(x, ln1g, ln1b, nullptr, h1h, h1l, nullptr);
    k_mma<0><<<dim3(18,64),256,SMEMSZ>>>(h1h,h1l,Bqh,Bql,nullptr,nullptr,nullptr,
                                         NT,3*CCH,CCH);
    k_flash<<<dim3(8,BH),256,FSM2>>>();
    cudaStreamWaitEvent(0, evP, 0);
    k_mma<1><<<dim3(6,64),256,SMEMSZ>>>(aoh,aol,Bph,Bpl,b_proj,x,x2, NT,CCH,CCH);
    // fused LN2 + router
    k_lnrouter<<<NT,256>>>(ln2g, ln2b, wr, br, wn, bn, temp, rno);
    // experts, single-stream z-batched ladder (round-13 schedule)
    cudaStreamWaitEvent(0, evE, 0);
    k_mmah<2><<<dim3(24,64,8),256,HSMEM>>>(h2f,0, nullptr,0, 99,
        Bd1, Bs1,(size_t)CCH*FF, 2, db1,sb1,
        nullptr, t1f, ZT1, NT,FF,CCH, tok, cnt);
    k_mmah<2><<<dim3(24,64,2),256,HSMEM>>>(t1f,ZT1, nullptr,0, 99,
        Bd2, nullptr,(size_t)FF*FF, 99, db2,nullptr,
        nullptr, t2f, ZT1, NT,FF,FF, nullptr, cnt);
    k_mmah<3><<<dim3(6,64,8),256,HSMEM>>>(t2f,ZT1, t1f,ZT1, 2,
        Bd3, Bs2,(size_t)CCH*FF, 2, db3,sb2,
        t3, nullptr, ZT3, NT,CCH,FF, nullptr, cnt);
    k_fin<<<NT,256>>>(t3, dlng, dlnb, slng, slnb, out);
}